// round 7
// baseline (speedup 1.0000x reference)
#include <cuda_runtime.h>
#include <mma.h>
#include <math.h>

using namespace nvcuda;

// Problem constants (B=2, S=2048, H=1024, E=8, I=4096, top-2)
#define NT 4096        // tokens = B*S
#define HD 1024        // hidden
#define NE 8           // experts
#define ID 4096        // intermediate
#define NSLOT (2 * NT) // total routed (token, expert) slots

// GEMM tiling
#define BM 128
#define BN 128
#define BK 16
#define LDA 20   // As leading dim (padded)
#define LDB 132  // Bs leading dim (padded)
#define RTILES 32  // NT / BM  (max row tiles per expert)

// ---------------- static device scratch (no runtime alloc) ----------------
__device__ int   g_counts[NE];
__device__ int   g_offsets[NE + 1];
__device__ int   g_tok[NE * NT];        // token id per (expert, slot)
__device__ int   g_meta_i[NT * 4];      // per token: e0, slot0, e1, slot1
__device__ float g_meta_w[NT * 2];      // per token: w0, w1
__device__ float g_hdn[(size_t)NSLOT * ID];  // 128 MB: silu(x@W1) rows (compacted)
__device__ float g_y[(size_t)NSLOT * HD];    // 32 MB: hdn@W2 rows (compacted)

// RN round fp32 -> tf32 (keep in fp32 register with low mantissa bits zeroed)
__device__ __forceinline__ float rtf32(float x) {
    unsigned u;
    asm("cvt.rna.tf32.f32 %0, %1;" : "=r"(u) : "f"(x));
    return __uint_as_float(u);
}

// ---------------- reset ----------------
__global__ void reset_kernel() {
    if (threadIdx.x < NE) g_counts[threadIdx.x] = 0;
}

// ---------------- gating: fp32 logits, top-2, slot assignment ----------------
__global__ void gate_kernel(const float* __restrict__ x, const float* __restrict__ Wg) {
    int warp = (blockIdx.x * blockDim.x + threadIdx.x) >> 5;
    int lane = threadIdx.x & 31;
    if (warp >= NT) return;
    const float* xr = x + (size_t)warp * HD;

    float acc[NE];
#pragma unroll
    for (int i = 0; i < NE; i++) acc[i] = 0.f;

    for (int j = lane; j < HD; j += 32) {
        float xv = xr[j];
        const float4* w4 = reinterpret_cast<const float4*>(Wg + j * NE);
        float4 wa = w4[0], wb = w4[1];
        acc[0] += xv * wa.x; acc[1] += xv * wa.y;
        acc[2] += xv * wa.z; acc[3] += xv * wa.w;
        acc[4] += xv * wb.x; acc[5] += xv * wb.y;
        acc[6] += xv * wb.z; acc[7] += xv * wb.w;
    }
#pragma unroll
    for (int i = 0; i < NE; i++) {
#pragma unroll
        for (int o = 16; o > 0; o >>= 1)
            acc[i] += __shfl_xor_sync(0xffffffffu, acc[i], o);
    }

    if (lane == 0) {
        // top-1: strict > keeps lowest index on ties (matches jax top_k)
        int i0 = 0; float m0 = acc[0];
#pragma unroll
        for (int i = 1; i < NE; i++) if (acc[i] > m0) { m0 = acc[i]; i0 = i; }
        int i1 = -1; float m1 = -1e30f;
#pragma unroll
        for (int i = 0; i < NE; i++)
            if (i != i0 && acc[i] > m1) { m1 = acc[i]; i1 = i; }

        // renormalized top-2 softmax weights: w0 = sigmoid(l0 - l1)
        float w0 = 1.f / (1.f + expf(m1 - m0));
        float w1 = 1.f - w0;

        int s0 = atomicAdd(&g_counts[i0], 1);
        int s1 = atomicAdd(&g_counts[i1], 1);
        g_tok[i0 * NT + s0] = warp;
        g_tok[i1 * NT + s1] = warp;
        g_meta_i[warp * 4 + 0] = i0;
        g_meta_i[warp * 4 + 1] = s0;
        g_meta_i[warp * 4 + 2] = i1;
        g_meta_i[warp * 4 + 3] = s1;
        g_meta_w[warp * 2 + 0] = w0;
        g_meta_w[warp * 2 + 1] = w1;
    }
}

// ---------------- prefix sum of counts ----------------
__global__ void prefix_kernel() {
    if (threadIdx.x == 0) {
        int s = 0;
        g_offsets[0] = 0;
        for (int e = 0; e < NE; e++) { s += g_counts[e]; g_offsets[e + 1] = s; }
    }
}

// ---------------- grouped GEMM up: hdn = silu(Xg @ W1[e] + b1[e]) ----------------
__global__ __launch_bounds__(256, 2) void gemm_up_kernel(
    const float* __restrict__ x, const float* __restrict__ W1,
    const float* __restrict__ b1)
{
    __shared__ __align__(16) float As[BM * LDA];
    __shared__ __align__(16) float Bs[BK * LDB];
    __shared__ int s_tok[BM];
    __shared__ __align__(16) float s_patch[8 * 16 * 20];

    int e  = blockIdx.x / RTILES;
    int rt = blockIdx.x % RTILES;
    int n_e = g_counts[e];
    int row0 = rt * BM;
    if (row0 >= n_e) return;
    int n0 = blockIdx.y * BN;
    int tid = threadIdx.x;

    if (tid < BM) {
        int gs = row0 + tid;
        s_tok[tid] = (gs < n_e) ? g_tok[e * NT + gs] : -1;
    }
    __syncthreads();

    int arow = tid >> 1;            // 0..127
    int aseg = (tid & 1) * 8;       // 0 or 8
    int brow = tid >> 4;            // 0..15
    int bcol = (tid & 15) * 8;      // 0..120

    const float* Wp = W1 + (size_t)e * HD * ID;

    int wrp = tid >> 5, wm = wrp >> 1, wn = wrp & 1, lane = tid & 31;

    wmma::fragment<wmma::accumulator, 16, 16, 8, float> c[2][4];
#pragma unroll
    for (int i = 0; i < 2; i++)
#pragma unroll
        for (int j = 0; j < 4; j++) wmma::fill_fragment(c[i][j], 0.f);

    float4 ra0, ra1, rb0, rb1;
    {   // prologue loads (k0 = 0)
        int tok = s_tok[arow];
        if (tok >= 0) {
            const float4* p = reinterpret_cast<const float4*>(x + (size_t)tok * HD + aseg);
            ra0 = p[0]; ra1 = p[1];
        } else { ra0 = make_float4(0,0,0,0); ra1 = ra0; }
        const float4* q = reinterpret_cast<const float4*>(Wp + (size_t)brow * ID + n0 + bcol);
        rb0 = q[0]; rb1 = q[1];
    }

    const int KT = HD / BK;  // 64
    for (int kt = 0; kt < KT; ++kt) {
        // stage (with RN tf32 rounding)
        float4 t0 = make_float4(rtf32(ra0.x), rtf32(ra0.y), rtf32(ra0.z), rtf32(ra0.w));
        float4 t1 = make_float4(rtf32(ra1.x), rtf32(ra1.y), rtf32(ra1.z), rtf32(ra1.w));
        float4 u0 = make_float4(rtf32(rb0.x), rtf32(rb0.y), rtf32(rb0.z), rtf32(rb0.w));
        float4 u1 = make_float4(rtf32(rb1.x), rtf32(rb1.y), rtf32(rb1.z), rtf32(rb1.w));
        *reinterpret_cast<float4*>(&As[arow * LDA + aseg])     = t0;
        *reinterpret_cast<float4*>(&As[arow * LDA + aseg + 4]) = t1;
        *reinterpret_cast<float4*>(&Bs[brow * LDB + bcol])     = u0;
        *reinterpret_cast<float4*>(&Bs[brow * LDB + bcol + 4]) = u1;
        __syncthreads();

        if (kt + 1 < KT) {  // prefetch next tile into registers
            int k0 = (kt + 1) * BK;
            int tok = s_tok[arow];
            if (tok >= 0) {
                const float4* p = reinterpret_cast<const float4*>(x + (size_t)tok * HD + k0 + aseg);
                ra0 = p[0]; ra1 = p[1];
            } else { ra0 = make_float4(0,0,0,0); ra1 = ra0; }
            const float4* q = reinterpret_cast<const float4*>(Wp + (size_t)(k0 + brow) * ID + n0 + bcol);
            rb0 = q[0]; rb1 = q[1];
        }

#pragma unroll
        for (int kk = 0; kk < 2; ++kk) {
            wmma::fragment<wmma::matrix_a, 16, 16, 8, wmma::precision::tf32, wmma::row_major> af[2];
            wmma::fragment<wmma::matrix_b, 16, 16, 8, wmma::precision::tf32, wmma::row_major> bf[4];
#pragma unroll
            for (int i = 0; i < 2; i++)
                wmma::load_matrix_sync(af[i], &As[(wm * 32 + i * 16) * LDA + kk * 8], LDA);
#pragma unroll
            for (int j = 0; j < 4; j++)
                wmma::load_matrix_sync(bf[j], &Bs[(kk * 8) * LDB + wn * 64 + j * 16], LDB);
#pragma unroll
            for (int i = 0; i < 2; i++)
#pragma unroll
                for (int j = 0; j < 4; j++)
                    wmma::mma_sync(c[i][j], af[i], bf[j], c[i][j]);
        }
        __syncthreads();
    }

    // epilogue: bias + silu, store compacted rows
    int base_row = g_offsets[e] + row0;
    const float* bias = b1 + e * ID;
    float* patch = &s_patch[wrp * 16 * 20];
#pragma unroll
    for (int i = 0; i < 2; i++) {
#pragma unroll
        for (int j = 0; j < 4; j++) {
            wmma::store_matrix_sync(patch, c[i][j], 20, wmma::mem_row_major);
            __syncwarp();
            int lrb = wm * 32 + i * 16;
            int lcb = wn * 64 + j * 16;
#pragma unroll
            for (int q = 0; q < 8; q++) {
                int el = lane + q * 32;
                int r = el >> 4, cc = el & 15;
                int lr = lrb + r;
                if (row0 + lr < n_e) {
                    int gc = n0 + lcb + cc;
                    float v = patch[r * 20 + cc] + bias[gc];
                    float sv = v / (1.f + expf(-v));
                    g_hdn[(size_t)(base_row + lr) * ID + gc] = sv;
                }
            }
            __syncwarp();
        }
    }
}

// ---------------- grouped GEMM down: y = hdn @ W2[e] ----------------
__global__ __launch_bounds__(256, 2) void gemm_down_kernel(const float* __restrict__ W2) {
    __shared__ __align__(16) float As[BM * LDA];
    __shared__ __align__(16) float Bs[BK * LDB];
    __shared__ __align__(16) float s_patch[8 * 16 * 20];

    int e  = blockIdx.x / RTILES;
    int rt = blockIdx.x % RTILES;
    int n_e = g_counts[e];
    int row0 = rt * BM;
    if (row0 >= n_e) return;
    int obase = g_offsets[e];
    int n0 = blockIdx.y * BN;
    int tid = threadIdx.x;

    int arow = tid >> 1;
    int aseg = (tid & 1) * 8;
    int brow = tid >> 4;
    int bcol = (tid & 15) * 8;

    const float* Wp = W2 + (size_t)e * ID * HD;

    int wrp = tid >> 5, wm = wrp >> 1, wn = wrp & 1, lane = tid & 31;

    wmma::fragment<wmma::accumulator, 16, 16, 8, float> c[2][4];
#pragma unroll
    for (int i = 0; i < 2; i++)
#pragma unroll
        for (int j = 0; j < 4; j++) wmma::fill_fragment(c[i][j], 0.f);

    bool avalid = (row0 + arow) < n_e;
    const float* arowp = g_hdn + (size_t)(obase + row0 + arow) * ID;

    float4 ra0, ra1, rb0, rb1;
    {
        if (avalid) {
            const float4* p = reinterpret_cast<const float4*>(arowp + aseg);
            ra0 = p[0]; ra1 = p[1];
        } else { ra0 = make_float4(0,0,0,0); ra1 = ra0; }
        const float4* q = reinterpret_cast<const float4*>(Wp + (size_t)brow * HD + n0 + bcol);
        rb0 = q[0]; rb1 = q[1];
    }

    const int KT = ID / BK;  // 256
    for (int kt = 0; kt < KT; ++kt) {
        float4 t0 = make_float4(rtf32(ra0.x), rtf32(ra0.y), rtf32(ra0.z), rtf32(ra0.w));
        float4 t1 = make_float4(rtf32(ra1.x), rtf32(ra1.y), rtf32(ra1.z), rtf32(ra1.w));
        float4 u0 = make_float4(rtf32(rb0.x), rtf32(rb0.y), rtf32(rb0.z), rtf32(rb0.w));
        float4 u1 = make_float4(rtf32(rb1.x), rtf32(rb1.y), rtf32(rb1.z), rtf32(rb1.w));
        *reinterpret_cast<float4*>(&As[arow * LDA + aseg])     = t0;
        *reinterpret_cast<float4*>(&As[arow * LDA + aseg + 4]) = t1;
        *reinterpret_cast<float4*>(&Bs[brow * LDB + bcol])     = u0;
        *reinterpret_cast<float4*>(&Bs[brow * LDB + bcol + 4]) = u1;
        __syncthreads();

        if (kt + 1 < KT) {
            int k0 = (kt + 1) * BK;
            if (avalid) {
                const float4* p = reinterpret_cast<const float4*>(arowp + k0 + aseg);
                ra0 = p[0]; ra1 = p[1];
            } else { ra0 = make_float4(0,0,0,0); ra1 = ra0; }
            const float4* q = reinterpret_cast<const float4*>(Wp + (size_t)(k0 + brow) * HD + n0 + bcol);
            rb0 = q[0]; rb1 = q[1];
        }

#pragma unroll
        for (int kk = 0; kk < 2; ++kk) {
            wmma::fragment<wmma::matrix_a, 16, 16, 8, wmma::precision::tf32, wmma::row_major> af[2];
            wmma::fragment<wmma::matrix_b, 16, 16, 8, wmma::precision::tf32, wmma::row_major> bf[4];
#pragma unroll
            for (int i = 0; i < 2; i++)
                wmma::load_matrix_sync(af[i], &As[(wm * 32 + i * 16) * LDA + kk * 8], LDA);
#pragma unroll
            for (int j = 0; j < 4; j++)
                wmma::load_matrix_sync(bf[j], &Bs[(kk * 8) * LDB + wn * 64 + j * 16], LDB);
#pragma unroll
            for (int i = 0; i < 2; i++)
#pragma unroll
                for (int j = 0; j < 4; j++)
                    wmma::mma_sync(c[i][j], af[i], bf[j], c[i][j]);
        }
        __syncthreads();
    }

    int base_row = obase + row0;
    float* patch = &s_patch[wrp * 16 * 20];
#pragma unroll
    for (int i = 0; i < 2; i++) {
#pragma unroll
        for (int j = 0; j < 4; j++) {
            wmma::store_matrix_sync(patch, c[i][j], 20, wmma::mem_row_major);
            __syncwarp();
            int lrb = wm * 32 + i * 16;
            int lcb = wn * 64 + j * 16;
#pragma unroll
            for (int q = 0; q < 8; q++) {
                int el = lane + q * 32;
                int r = el >> 4, cc = el & 15;
                int lr = lrb + r;
                if (row0 + lr < n_e) {
                    int gc = n0 + lcb + cc;
                    g_y[(size_t)(base_row + lr) * HD + gc] = patch[r * 20 + cc];
                }
            }
            __syncwarp();
        }
    }
}

// ---------------- deterministic per-token combine ----------------
__global__ void combine_kernel(const float* __restrict__ b2, float* __restrict__ out) {
    int t = blockIdx.x;
    int e0 = g_meta_i[t * 4 + 0], s0 = g_meta_i[t * 4 + 1];
    int e1 = g_meta_i[t * 4 + 2], s1 = g_meta_i[t * 4 + 3];
    float w0 = g_meta_w[t * 2 + 0];
    float w1 = g_meta_w[t * 2 + 1];
    int r0 = g_offsets[e0] + s0;
    int r1 = g_offsets[e1] + s1;

    const float4* y0 = reinterpret_cast<const float4*>(g_y + (size_t)r0 * HD);
    const float4* y1 = reinterpret_cast<const float4*>(g_y + (size_t)r1 * HD);
    const float4* c0 = reinterpret_cast<const float4*>(b2 + (size_t)e0 * HD);
    const float4* c1 = reinterpret_cast<const float4*>(b2 + (size_t)e1 * HD);
    float4* o = reinterpret_cast<float4*>(out + (size_t)t * HD);

    int h = threadIdx.x;  // blockDim = 256 == HD/4
    float4 a = y0[h], b = y1[h], p = c0[h], q = c1[h];
    float4 r;
    r.x = w0 * (a.x + p.x) + w1 * (b.x + q.x);
    r.y = w0 * (a.y + p.y) + w1 * (b.y + q.y);
    r.z = w0 * (a.z + p.z) + w1 * (b.z + q.z);
    r.w = w0 * (a.w + p.w) + w1 * (b.w + q.w);
    o[h] = r;
}

// ---------------- launch ----------------
extern "C" void kernel_launch(void* const* d_in, const int* in_sizes, int n_in,
                              void* d_out, int out_size) {
    const float* x  = (const float*)d_in[0];
    const float* Wg = (const float*)d_in[1];
    const float* W1 = (const float*)d_in[2];
    const float* b1 = (const float*)d_in[3];
    const float* W2 = (const float*)d_in[4];
    const float* b2 = (const float*)d_in[5];
    float* out = (float*)d_out;

    reset_kernel<<<1, 32>>>();
    gate_kernel<<<NT / 8, 256>>>(x, Wg);            // 8 warps/block, 1 warp/token
    prefix_kernel<<<1, 32>>>();
    gemm_up_kernel<<<dim3(NE * RTILES, ID / BN), 256>>>(x, W1, b1);
    gemm_down_kernel<<<dim3(NE * RTILES, HD / BN), 256>>>(W2);
    combine_kernel<<<NT, 256>>>(b2, out);
}

// round 8
// speedup vs baseline: 1.0042x; 1.0042x over previous
#include <cuda_runtime.h>
#include <mma.h>
#include <math.h>

using namespace nvcuda;

// Problem constants (B=2, S=2048, H=1024, E=8, I=4096, top-2)
#define NT 4096        // tokens = B*S
#define HD 1024        // hidden
#define NE 8           // experts
#define ID 4096        // intermediate
#define NSLOT (2 * NT) // total routed (token, expert) slots

// GEMM tiling
#define BM 128
#define BN 128
#define BK 16
#define LDA 20   // As leading dim (padded)
#define LDB 132  // Bs leading dim (padded)
#define RTILES 32  // NT / BM  (max row tiles per expert)

#define ASZ (BM * LDA)        // 2560 floats
#define BSZ (BK * LDB)        // 2112 floats
#define STAGE_F (ASZ + BSZ)   // 4672 floats per stage

// ---------------- static device scratch (no runtime alloc) ----------------
__device__ int   g_counts[NE];
__device__ int   g_offsets[NE + 1];
__device__ int   g_tok[NE * NT];        // token id per (expert, slot)
__device__ int   g_meta_i[NT * 4];      // per token: e0, slot0, e1, slot1
__device__ float g_meta_w[NT * 2];      // per token: w0, w1
__device__ float g_hdn[(size_t)NSLOT * ID];  // 128 MB: silu(x@W1) rows (compacted)
__device__ float g_y[(size_t)NSLOT * HD];    // 32 MB: hdn@W2 rows (compacted)

// RN round fp32 -> tf32 (keep in fp32 register with low mantissa bits zeroed)
__device__ __forceinline__ float rtf32(float x) {
    unsigned u;
    asm("cvt.rna.tf32.f32 %0, %1;" : "=r"(u) : "f"(x));
    return __uint_as_float(u);
}

__device__ __forceinline__ float4 rtf32_4(float4 v) {
    return make_float4(rtf32(v.x), rtf32(v.y), rtf32(v.z), rtf32(v.w));
}

// ---------------- reset ----------------
__global__ void reset_kernel() {
    if (threadIdx.x < NE) g_counts[threadIdx.x] = 0;
}

// ---------------- gating: fp32 logits, top-2, slot assignment ----------------
__global__ void gate_kernel(const float* __restrict__ x, const float* __restrict__ Wg) {
    int warp = (blockIdx.x * blockDim.x + threadIdx.x) >> 5;
    int lane = threadIdx.x & 31;
    if (warp >= NT) return;
    const float* xr = x + (size_t)warp * HD;

    float acc[NE];
#pragma unroll
    for (int i = 0; i < NE; i++) acc[i] = 0.f;

    for (int j = lane; j < HD; j += 32) {
        float xv = xr[j];
        const float4* w4 = reinterpret_cast<const float4*>(Wg + j * NE);
        float4 wa = w4[0], wb = w4[1];
        acc[0] += xv * wa.x; acc[1] += xv * wa.y;
        acc[2] += xv * wa.z; acc[3] += xv * wa.w;
        acc[4] += xv * wb.x; acc[5] += xv * wb.y;
        acc[6] += xv * wb.z; acc[7] += xv * wb.w;
    }
#pragma unroll
    for (int i = 0; i < NE; i++) {
#pragma unroll
        for (int o = 16; o > 0; o >>= 1)
            acc[i] += __shfl_xor_sync(0xffffffffu, acc[i], o);
    }

    if (lane == 0) {
        // top-1: strict > keeps lowest index on ties (matches jax top_k)
        int i0 = 0; float m0 = acc[0];
#pragma unroll
        for (int i = 1; i < NE; i++) if (acc[i] > m0) { m0 = acc[i]; i0 = i; }
        int i1 = -1; float m1 = -1e30f;
#pragma unroll
        for (int i = 0; i < NE; i++)
            if (i != i0 && acc[i] > m1) { m1 = acc[i]; i1 = i; }

        // renormalized top-2 softmax weights: w0 = sigmoid(l0 - l1)
        float w0 = 1.f / (1.f + expf(m1 - m0));
        float w1 = 1.f - w0;

        int s0 = atomicAdd(&g_counts[i0], 1);
        int s1 = atomicAdd(&g_counts[i1], 1);
        g_tok[i0 * NT + s0] = warp;
        g_tok[i1 * NT + s1] = warp;
        g_meta_i[warp * 4 + 0] = i0;
        g_meta_i[warp * 4 + 1] = s0;
        g_meta_i[warp * 4 + 2] = i1;
        g_meta_i[warp * 4 + 3] = s1;
        g_meta_w[warp * 2 + 0] = w0;
        g_meta_w[warp * 2 + 1] = w1;
    }
}

// ---------------- prefix sum of counts ----------------
__global__ void prefix_kernel() {
    if (threadIdx.x == 0) {
        int s = 0;
        g_offsets[0] = 0;
        for (int e = 0; e < NE; e++) { s += g_counts[e]; g_offsets[e + 1] = s; }
    }
}

// ---------------- grouped GEMM up: hdn = silu(Xg @ W1[e] + b1[e]) ----------------
__global__ __launch_bounds__(256, 2) void gemm_up_kernel(
    const float* __restrict__ x, const float* __restrict__ W1,
    const float* __restrict__ b1)
{
    __shared__ __align__(16) float sh[2 * STAGE_F];  // double-buffered As+Bs
    __shared__ int s_tok[BM];

    int e  = blockIdx.x / RTILES;
    int rt = blockIdx.x % RTILES;
    int n_e = g_counts[e];
    int row0 = rt * BM;
    if (row0 >= n_e) return;
    int n0 = blockIdx.y * BN;
    int tid = threadIdx.x;

    if (tid < BM) {
        int gs = row0 + tid;
        s_tok[tid] = (gs < n_e) ? g_tok[e * NT + gs] : -1;
    }
    __syncthreads();

    int arow = tid >> 1;            // 0..127
    int aseg = (tid & 1) * 8;       // 0 or 8
    int brow = tid >> 4;            // 0..15
    int bcol = (tid & 15) * 8;      // 0..120

    const float* Wp = W1 + (size_t)e * HD * ID;
    int my_tok = s_tok[arow];
    const float* xrow = (my_tok >= 0) ? (x + (size_t)my_tok * HD) : nullptr;

    int wrp = tid >> 5, wm = wrp >> 1, wn = wrp & 1, lane = tid & 31;

    wmma::fragment<wmma::accumulator, 16, 16, 8, float> c[2][4];
#pragma unroll
    for (int i = 0; i < 2; i++)
#pragma unroll
        for (int j = 0; j < 4; j++) wmma::fill_fragment(c[i][j], 0.f);

    float4 ra0, ra1, rb0, rb1;

    // load k-tile kt into registers
    auto loadreg = [&](int kt) {
        int k0 = kt * BK;
        if (xrow) {
            const float4* p = reinterpret_cast<const float4*>(xrow + k0 + aseg);
            ra0 = p[0]; ra1 = p[1];
        } else { ra0 = make_float4(0,0,0,0); ra1 = ra0; }
        const float4* q = reinterpret_cast<const float4*>(Wp + (size_t)(k0 + brow) * ID + n0 + bcol);
        rb0 = q[0]; rb1 = q[1];
    };
    // store registers (RN tf32-rounded) into stage s
    auto storestage = [&](int s) {
        float* As = &sh[s * STAGE_F];
        float* Bs = &sh[s * STAGE_F + ASZ];
        *reinterpret_cast<float4*>(&As[arow * LDA + aseg])     = rtf32_4(ra0);
        *reinterpret_cast<float4*>(&As[arow * LDA + aseg + 4]) = rtf32_4(ra1);
        *reinterpret_cast<float4*>(&Bs[brow * LDB + bcol])     = rtf32_4(rb0);
        *reinterpret_cast<float4*>(&Bs[brow * LDB + bcol + 4]) = rtf32_4(rb1);
    };

    const int KT = HD / BK;  // 64
    loadreg(0);
    storestage(0);
    loadreg(1);
    __syncthreads();

    for (int kt = 0; kt < KT; ++kt) {
        if (kt + 1 < KT) {
            storestage((kt + 1) & 1);          // regs hold kt+1 data
            if (kt + 2 < KT) loadreg(kt + 2);  // prefetch; latency hidden by MMAs
        }
        const float* As = &sh[(kt & 1) * STAGE_F];
        const float* Bs = &sh[(kt & 1) * STAGE_F + ASZ];
#pragma unroll
        for (int kk = 0; kk < 2; ++kk) {
            wmma::fragment<wmma::matrix_a, 16, 16, 8, wmma::precision::tf32, wmma::row_major> af[2];
            wmma::fragment<wmma::matrix_b, 16, 16, 8, wmma::precision::tf32, wmma::row_major> bf[4];
#pragma unroll
            for (int i = 0; i < 2; i++)
                wmma::load_matrix_sync(af[i], &As[(wm * 32 + i * 16) * LDA + kk * 8], LDA);
#pragma unroll
            for (int j = 0; j < 4; j++)
                wmma::load_matrix_sync(bf[j], &Bs[(kk * 8) * LDB + wn * 64 + j * 16], LDB);
#pragma unroll
            for (int i = 0; i < 2; i++)
#pragma unroll
                for (int j = 0; j < 4; j++)
                    wmma::mma_sync(c[i][j], af[i], bf[j], c[i][j]);
        }
        __syncthreads();  // single barrier per K-slice
    }

    // epilogue: bias + silu, store compacted rows (patch overlays stage 0 — dead now)
    int base_row = g_offsets[e] + row0;
    const float* bias = b1 + e * ID;
    float* patch = &sh[wrp * 16 * 20];
#pragma unroll
    for (int i = 0; i < 2; i++) {
#pragma unroll
        for (int j = 0; j < 4; j++) {
            wmma::store_matrix_sync(patch, c[i][j], 20, wmma::mem_row_major);
            __syncwarp();
            int lrb = wm * 32 + i * 16;
            int lcb = wn * 64 + j * 16;
#pragma unroll
            for (int q = 0; q < 8; q++) {
                int el = lane + q * 32;
                int r = el >> 4, cc = el & 15;
                int lr = lrb + r;
                if (row0 + lr < n_e) {
                    int gc = n0 + lcb + cc;
                    float v = patch[r * 20 + cc] + bias[gc];
                    float sv = v / (1.f + expf(-v));
                    g_hdn[(size_t)(base_row + lr) * ID + gc] = sv;
                }
            }
            __syncwarp();
        }
    }
}

// ---------------- grouped GEMM down: y = hdn @ W2[e] ----------------
__global__ __launch_bounds__(256, 2) void gemm_down_kernel(const float* __restrict__ W2) {
    __shared__ __align__(16) float sh[2 * STAGE_F];

    int e  = blockIdx.x / RTILES;
    int rt = blockIdx.x % RTILES;
    int n_e = g_counts[e];
    int row0 = rt * BM;
    if (row0 >= n_e) return;
    int obase = g_offsets[e];
    int n0 = blockIdx.y * BN;
    int tid = threadIdx.x;

    int arow = tid >> 1;
    int aseg = (tid & 1) * 8;
    int brow = tid >> 4;
    int bcol = (tid & 15) * 8;

    const float* Wp = W2 + (size_t)e * ID * HD;

    int wrp = tid >> 5, wm = wrp >> 1, wn = wrp & 1, lane = tid & 31;

    wmma::fragment<wmma::accumulator, 16, 16, 8, float> c[2][4];
#pragma unroll
    for (int i = 0; i < 2; i++)
#pragma unroll
        for (int j = 0; j < 4; j++) wmma::fill_fragment(c[i][j], 0.f);

    bool avalid = (row0 + arow) < n_e;
    const float* arowp = g_hdn + (size_t)(obase + row0 + arow) * ID;

    float4 ra0, ra1, rb0, rb1;

    auto loadreg = [&](int kt) {
        int k0 = kt * BK;
        if (avalid) {
            const float4* p = reinterpret_cast<const float4*>(arowp + k0 + aseg);
            ra0 = p[0]; ra1 = p[1];
        } else { ra0 = make_float4(0,0,0,0); ra1 = ra0; }
        const float4* q = reinterpret_cast<const float4*>(Wp + (size_t)(k0 + brow) * HD + n0 + bcol);
        rb0 = q[0]; rb1 = q[1];
    };
    auto storestage = [&](int s) {
        float* As = &sh[s * STAGE_F];
        float* Bs = &sh[s * STAGE_F + ASZ];
        *reinterpret_cast<float4*>(&As[arow * LDA + aseg])     = rtf32_4(ra0);
        *reinterpret_cast<float4*>(&As[arow * LDA + aseg + 4]) = rtf32_4(ra1);
        *reinterpret_cast<float4*>(&Bs[brow * LDB + bcol])     = rtf32_4(rb0);
        *reinterpret_cast<float4*>(&Bs[brow * LDB + bcol + 4]) = rtf32_4(rb1);
    };

    const int KT = ID / BK;  // 256
    loadreg(0);
    storestage(0);
    loadreg(1);
    __syncthreads();

    for (int kt = 0; kt < KT; ++kt) {
        if (kt + 1 < KT) {
            storestage((kt + 1) & 1);
            if (kt + 2 < KT) loadreg(kt + 2);
        }
        const float* As = &sh[(kt & 1) * STAGE_F];
        const float* Bs = &sh[(kt & 1) * STAGE_F + ASZ];
#pragma unroll
        for (int kk = 0; kk < 2; ++kk) {
            wmma::fragment<wmma::matrix_a, 16, 16, 8, wmma::precision::tf32, wmma::row_major> af[2];
            wmma::fragment<wmma::matrix_b, 16, 16, 8, wmma::precision::tf32, wmma::row_major> bf[4];
#pragma unroll
            for (int i = 0; i < 2; i++)
                wmma::load_matrix_sync(af[i], &As[(wm * 32 + i * 16) * LDA + kk * 8], LDA);
#pragma unroll
            for (int j = 0; j < 4; j++)
                wmma::load_matrix_sync(bf[j], &Bs[(kk * 8) * LDB + wn * 64 + j * 16], LDB);
#pragma unroll
            for (int i = 0; i < 2; i++)
#pragma unroll
                for (int j = 0; j < 4; j++)
                    wmma::mma_sync(c[i][j], af[i], bf[j], c[i][j]);
        }
        __syncthreads();
    }

    int base_row = obase + row0;
    float* patch = &sh[wrp * 16 * 20];  // overlays stage 0 (dead after last barrier)
#pragma unroll
    for (int i = 0; i < 2; i++) {
#pragma unroll
        for (int j = 0; j < 4; j++) {
            wmma::store_matrix_sync(patch, c[i][j], 20, wmma::mem_row_major);
            __syncwarp();
            int lrb = wm * 32 + i * 16;
            int lcb = wn * 64 + j * 16;
#pragma unroll
            for (int q = 0; q < 8; q++) {
                int el = lane + q * 32;
                int r = el >> 4, cc = el & 15;
                int lr = lrb + r;
                if (row0 + lr < n_e) {
                    int gc = n0 + lcb + cc;
                    g_y[(size_t)(base_row + lr) * HD + gc] = patch[r * 20 + cc];
                }
            }
            __syncwarp();
        }
    }
}

// ---------------- deterministic per-token combine ----------------
__global__ void combine_kernel(const float* __restrict__ b2, float* __restrict__ out) {
    int t = blockIdx.x;
    int e0 = g_meta_i[t * 4 + 0], s0 = g_meta_i[t * 4 + 1];
    int e1 = g_meta_i[t * 4 + 2], s1 = g_meta_i[t * 4 + 3];
    float w0 = g_meta_w[t * 2 + 0];
    float w1 = g_meta_w[t * 2 + 1];
    int r0 = g_offsets[e0] + s0;
    int r1 = g_offsets[e1] + s1;

    const float4* y0 = reinterpret_cast<const float4*>(g_y + (size_t)r0 * HD);
    const float4* y1 = reinterpret_cast<const float4*>(g_y + (size_t)r1 * HD);
    const float4* c0 = reinterpret_cast<const float4*>(b2 + (size_t)e0 * HD);
    const float4* c1 = reinterpret_cast<const float4*>(b2 + (size_t)e1 * HD);
    float4* o = reinterpret_cast<float4*>(out + (size_t)t * HD);

    int h = threadIdx.x;  // blockDim = 256 == HD/4
    float4 a = y0[h], b = y1[h], p = c0[h], q = c1[h];
    float4 r;
    r.x = w0 * (a.x + p.x) + w1 * (b.x + q.x);
    r.y = w0 * (a.y + p.y) + w1 * (b.y + q.y);
    r.z = w0 * (a.z + p.z) + w1 * (b.z + q.z);
    r.w = w0 * (a.w + p.w) + w1 * (b.w + q.w);
    o[h] = r;
}

// ---------------- launch ----------------
extern "C" void kernel_launch(void* const* d_in, const int* in_sizes, int n_in,
                              void* d_out, int out_size) {
    const float* x  = (const float*)d_in[0];
    const float* Wg = (const float*)d_in[1];
    const float* W1 = (const float*)d_in[2];
    const float* b1 = (const float*)d_in[3];
    const float* W2 = (const float*)d_in[4];
    const float* b2 = (const float*)d_in[5];
    float* out = (float*)d_out;

    reset_kernel<<<1, 32>>>();
    gate_kernel<<<NT / 8, 256>>>(x, Wg);            // 8 warps/block, 1 warp/token
    prefix_kernel<<<1, 32>>>();
    gemm_up_kernel<<<dim3(NE * RTILES, ID / BN), 256>>>(x, W1, b1);
    gemm_down_kernel<<<dim3(NE * RTILES, HD / BN), 256>>>(W2);
    combine_kernel<<<NT, 256>>>(b2, out);
}